// round 10
// baseline (speedup 1.0000x reference)
#include <cuda_runtime.h>

#define NN 50000
#define EE 800000

// ---------------- scratch (device globals; no allocations allowed) ----------
__device__ float g_h[NN * 128];      // transformed features of current layer [N, H*C]
__device__ float g_out[NN * 128];    // aggregated output / next-layer input
__device__ float g_asrc[NN * 4];     // per-head src attention logits
__device__ float g_adst[NN * 4];     // per-head dst attention logits
__device__ float g_ssum[NN * 4];     // per-head softmax denominators
__device__ int   g_is64;             // edge_index dtype flag (1 = int64, 0 = int32)

__device__ __forceinline__ float lrelu(float x) { return x > 0.f ? x : 0.2f * x; }

__device__ __forceinline__ int eidx(const void* ei, int pos, int is64) {
    if (is64) return (int)((const long long*)ei)[pos];
    return ((const int*)ei)[pos];
}

// vectorized fire-and-forget atomic add (sm_90+)
__device__ __forceinline__ void red4(float* addr, float a, float b, float c, float d) {
    asm volatile("red.global.add.v4.f32 [%0], {%1, %2, %3, %4};"
                 :: "l"(addr), "f"(a), "f"(b), "f"(c), "f"(d) : "memory");
}

// ---------------- dtype detection -------------------------------------------
// If edge_index is int64, all high 32-bit words are 0 (values < 50000, nonneg).
// If int32, the odd words are random node ids (~0 chance all 1024 are zero).
__global__ void detect_k(const unsigned int* ei) {
    __shared__ int any;
    if (threadIdx.x == 0) any = 0;
    __syncthreads();
    int bad = 0;
    for (int i = threadIdx.x; i < 1024; i += blockDim.x)
        if (ei[2 * i + 1] != 0u) bad = 1;
    if (bad) any = 1;
    __syncthreads();
    if (threadIdx.x == 0) g_is64 = any ? 0 : 1;
}

__global__ void zero_k(float* p, int n) {
    int i = blockIdx.x * blockDim.x + threadIdx.x;
    if (i < n) p[i] = 0.f;
}

// ---------------- fused GEMM + attention projections ------------------------
// h[n, :] = in[n, :] @ W ;  a_src[n,h] = <h[n,h,:], att_src[h,:]> (same for dst)
// block = 128 threads handles (128/HC) nodes; per-head reduce via shfl over C lanes.
template <int K, int HC, int C>
__global__ void gemm_att_k(const float* __restrict__ in, const float* __restrict__ W,
                           const float* __restrict__ ats, const float* __restrict__ atd) {
    constexpr int NPB = 128 / HC;
    __shared__ float s_in[NPB * K];
    int n0 = blockIdx.x * NPB;
    for (int i = threadIdx.x; i < NPB * K; i += 128)
        s_in[i] = in[(n0 + i / K) * K + (i % K)];
    __syncthreads();

    int local = threadIdx.x / HC;
    int col   = threadIdx.x % HC;
    int n     = n0 + local;

    float acc = 0.f;
#pragma unroll
    for (int k = 0; k < K; k++)
        acc += s_in[local * K + k] * W[k * HC + col];
    g_h[n * HC + col] = acc;

    float vs = acc * ats[col];
    float vd = acc * atd[col];
#pragma unroll
    for (int off = C / 2; off > 0; off >>= 1) {
        vs += __shfl_xor_sync(0xffffffffu, vs, off);
        vd += __shfl_xor_sync(0xffffffffu, vd, off);
    }
    if ((col & (C - 1)) == 0) {
        int head = col / C;
        g_asrc[n * 4 + head] = vs;
        g_adst[n * 4 + head] = vd;
    }
}

// ---------------- edge pass A: softmax denominators --------------------------
__global__ void edgeA_k(const void* __restrict__ ei) {
    int e = blockIdx.x * blockDim.x + threadIdx.x;
    if (e >= EE) return;
    int is64 = g_is64;
    int s = eidx(ei, e, is64);
    int d = eidx(ei, EE + e, is64);
    float4 as = *(const float4*)&g_asrc[s * 4];
    float4 ad = *(const float4*)&g_adst[d * 4];
    float px = __expf(lrelu(as.x + ad.x));
    float py = __expf(lrelu(as.y + ad.y));
    float pz = __expf(lrelu(as.z + ad.z));
    float pw = __expf(lrelu(as.w + ad.w));
    red4(&g_ssum[d * 4], px, py, pz, pw);
}

// ---------------- edge pass B: weighted message scatter -----------------------
// HC/4 threads per edge; each thread moves one float4 of h[src] into out[dst].
template <int HC, int C>
__global__ void edgeB_k(const void* __restrict__ ei) {
    constexpr int T = HC / 4;
    int t = blockIdx.x * blockDim.x + threadIdx.x;
    int e = t / T;
    if (e >= EE) return;
    int lane = t % T;
    int is64 = g_is64;
    int s = eidx(ei, e, is64);
    int d = eidx(ei, EE + e, is64);
    int head = (lane * 4) / C;
    float a  = g_asrc[s * 4 + head] + g_adst[d * 4 + head];
    float ss = g_ssum[d * 4 + head];
    float alpha = __expf(lrelu(a)) / (ss + 1e-16f);
    float4 hv = *(const float4*)&g_h[s * HC + lane * 4];
    red4(&g_out[d * HC + lane * 4],
         hv.x * alpha, hv.y * alpha, hv.z * alpha, hv.w * alpha);
}

// ---------------- bias + ELU (in place on g_out) -----------------------------
template <int HC>
__global__ void bias_elu_k(const float* __restrict__ bias) {
    int i = blockIdx.x * blockDim.x + threadIdx.x;
    if (i >= NN * HC) return;
    float v = g_out[i] + bias[i % HC];
    g_out[i] = v > 0.f ? v : expm1f(v);
}

// ---------------- final layer: head-mean + bias -> d_out ---------------------
__global__ void final_k(const float* __restrict__ b3, float* __restrict__ out) {
    int i = blockIdx.x * blockDim.x + threadIdx.x;
    if (i >= NN * 32) return;
    int n = i >> 5, c = i & 31;
    const float* r = &g_out[n * 128];
    out[i] = 0.25f * (r[c] + r[32 + c] + r[64 + c] + r[96 + c]) + b3[c];
}

// -----------------------------------------------------------------------------
extern "C" void kernel_launch(void* const* d_in, const int* in_sizes, int n_in,
                              void* d_out, int out_size) {
    const float* x   = (const float*)d_in[0];
    const void*  ei  = d_in[1];
    const float* W1  = (const float*)d_in[2];
    const float* as1 = (const float*)d_in[3];
    const float* ad1 = (const float*)d_in[4];
    const float* b1  = (const float*)d_in[5];
    const float* W2  = (const float*)d_in[6];
    const float* as2 = (const float*)d_in[7];
    const float* ad2 = (const float*)d_in[8];
    const float* b2  = (const float*)d_in[9];
    const float* W3  = (const float*)d_in[10];
    const float* as3 = (const float*)d_in[11];
    const float* ad3 = (const float*)d_in[12];
    const float* b3  = (const float*)d_in[13];

    float *p_out, *p_ssum;
    cudaGetSymbolAddress((void**)&p_out, g_out);
    cudaGetSymbolAddress((void**)&p_ssum, g_ssum);

    detect_k<<<1, 256>>>((const unsigned int*)ei);

    // ---- layer 1: 128 -> 4x8 (concat 32), ELU ----
    gemm_att_k<128, 32, 8><<<NN / 4, 128>>>(x, W1, as1, ad1);
    zero_k<<<(NN * 4 + 255) / 256, 256>>>(p_ssum, NN * 4);
    zero_k<<<(NN * 32 + 255) / 256, 256>>>(p_out, NN * 32);
    edgeA_k<<<(EE + 255) / 256, 256>>>(ei);
    edgeB_k<32, 8><<<(EE * 8 + 255) / 256, 256>>>(ei);
    bias_elu_k<32><<<(NN * 32 + 255) / 256, 256>>>(b1);

    // ---- layer 2: 32 -> 4x32 (concat 128), ELU ----
    gemm_att_k<32, 128, 32><<<NN, 128>>>(p_out, W2, as2, ad2);
    zero_k<<<(NN * 4 + 255) / 256, 256>>>(p_ssum, NN * 4);
    zero_k<<<(NN * 128 + 255) / 256, 256>>>(p_out, NN * 128);
    edgeA_k<<<(EE + 255) / 256, 256>>>(ei);
    edgeB_k<128, 32><<<(EE * 32 + 255) / 256, 256>>>(ei);
    bias_elu_k<128><<<(NN * 128 + 255) / 256, 256>>>(b2);

    // ---- layer 3: 128 -> 4x32, mean over heads, + b3 ----
    gemm_att_k<128, 128, 32><<<NN, 128>>>(p_out, W3, as3, ad3);
    zero_k<<<(NN * 4 + 255) / 256, 256>>>(p_ssum, NN * 4);
    zero_k<<<(NN * 128 + 255) / 256, 256>>>(p_out, NN * 128);
    edgeA_k<<<(EE + 255) / 256, 256>>>(ei);
    edgeB_k<128, 32><<<(EE * 32 + 255) / 256, 256>>>(ei);
    final_k<<<(NN * 32 + 255) / 256, 256>>>(b3, (float*)d_out);
}

// round 11
// speedup vs baseline: 1.0012x; 1.0012x over previous
#include <cuda_runtime.h>

#define NN 50000
#define EE 800000

// ---------------- scratch (device globals; no allocations allowed) ----------
__device__ float g_h[NN * 128];      // transformed features of current layer [N, H*C]
__device__ float g_out[NN * 128];    // aggregated output / next-layer input
__device__ float g_asrc[NN * 4];     // per-head src attention logits
__device__ float g_adst[NN * 4];     // per-head dst attention logits
__device__ float g_ssum[NN * 4];     // per-head softmax denominators
__device__ int   g_is64;             // edge_index dtype flag (1 = int64, 0 = int32)

__device__ __forceinline__ float lrelu(float x) { return x > 0.f ? x : 0.2f * x; }

__device__ __forceinline__ int eidx(const void* ei, int pos, int is64) {
    if (is64) return (int)((const long long*)ei)[pos];
    return ((const int*)ei)[pos];
}

// vectorized fire-and-forget atomic add (sm_90+)
__device__ __forceinline__ void red4(float* addr, float a, float b, float c, float d) {
    asm volatile("red.global.add.v4.f32 [%0], {%1, %2, %3, %4};"
                 :: "l"(addr), "f"(a), "f"(b), "f"(c), "f"(d) : "memory");
}

// ---------------- dtype detection -------------------------------------------
// If edge_index is int64, all high 32-bit words are 0 (values < 50000, nonneg).
// If int32, the odd words are random node ids (~0 chance all 1024 are zero).
__global__ void detect_k(const unsigned int* ei) {
    __shared__ int any;
    if (threadIdx.x == 0) any = 0;
    __syncthreads();
    int bad = 0;
    for (int i = threadIdx.x; i < 1024; i += blockDim.x)
        if (ei[2 * i + 1] != 0u) bad = 1;
    if (bad) any = 1;
    __syncthreads();
    if (threadIdx.x == 0) g_is64 = any ? 0 : 1;
}

__global__ void zero_k(float* p, int n) {
    int i = blockIdx.x * blockDim.x + threadIdx.x;
    if (i < n) p[i] = 0.f;
}

// ---------------- fused GEMM + attention projections ------------------------
// h[n, :] = in[n, :] @ W ;  a_src[n,h] = <h[n,h,:], att_src[h,:]> (same for dst)
// block = 128 threads handles (128/HC) nodes; per-head reduce via shfl over C lanes.
template <int K, int HC, int C>
__global__ void gemm_att_k(const float* __restrict__ in, const float* __restrict__ W,
                           const float* __restrict__ ats, const float* __restrict__ atd) {
    constexpr int NPB = 128 / HC;
    __shared__ float s_in[NPB * K];
    int n0 = blockIdx.x * NPB;
    for (int i = threadIdx.x; i < NPB * K; i += 128)
        s_in[i] = in[(n0 + i / K) * K + (i % K)];
    __syncthreads();

    int local = threadIdx.x / HC;
    int col   = threadIdx.x % HC;
    int n     = n0 + local;

    float acc = 0.f;
#pragma unroll
    for (int k = 0; k < K; k++)
        acc += s_in[local * K + k] * W[k * HC + col];
    g_h[n * HC + col] = acc;

    float vs = acc * ats[col];
    float vd = acc * atd[col];
#pragma unroll
    for (int off = C / 2; off > 0; off >>= 1) {
        vs += __shfl_xor_sync(0xffffffffu, vs, off);
        vd += __shfl_xor_sync(0xffffffffu, vd, off);
    }
    if ((col & (C - 1)) == 0) {
        int head = col / C;
        g_asrc[n * 4 + head] = vs;
        g_adst[n * 4 + head] = vd;
    }
}

// ---------------- edge pass A: softmax denominators --------------------------
__global__ void edgeA_k(const void* __restrict__ ei) {
    int e = blockIdx.x * blockDim.x + threadIdx.x;
    if (e >= EE) return;
    int is64 = g_is64;
    int s = eidx(ei, e, is64);
    int d = eidx(ei, EE + e, is64);
    float4 as = *(const float4*)&g_asrc[s * 4];
    float4 ad = *(const float4*)&g_adst[d * 4];
    float px = __expf(lrelu(as.x + ad.x));
    float py = __expf(lrelu(as.y + ad.y));
    float pz = __expf(lrelu(as.z + ad.z));
    float pw = __expf(lrelu(as.w + ad.w));
    red4(&g_ssum[d * 4], px, py, pz, pw);
}

// ---------------- edge pass B: weighted message scatter -----------------------
// HC/4 threads per edge; each thread moves one float4 of h[src] into out[dst].
template <int HC, int C>
__global__ void edgeB_k(const void* __restrict__ ei) {
    constexpr int T = HC / 4;
    int t = blockIdx.x * blockDim.x + threadIdx.x;
    int e = t / T;
    if (e >= EE) return;
    int lane = t % T;
    int is64 = g_is64;
    int s = eidx(ei, e, is64);
    int d = eidx(ei, EE + e, is64);
    int head = (lane * 4) / C;
    float a  = g_asrc[s * 4 + head] + g_adst[d * 4 + head];
    float ss = g_ssum[d * 4 + head];
    float alpha = __expf(lrelu(a)) / (ss + 1e-16f);
    float4 hv = *(const float4*)&g_h[s * HC + lane * 4];
    red4(&g_out[d * HC + lane * 4],
         hv.x * alpha, hv.y * alpha, hv.z * alpha, hv.w * alpha);
}

// ---------------- bias + ELU (in place on g_out) -----------------------------
template <int HC>
__global__ void bias_elu_k(const float* __restrict__ bias) {
    int i = blockIdx.x * blockDim.x + threadIdx.x;
    if (i >= NN * HC) return;
    float v = g_out[i] + bias[i % HC];
    g_out[i] = v > 0.f ? v : expm1f(v);
}

// ---------------- final layer: head-mean + bias -> d_out ---------------------
__global__ void final_k(const float* __restrict__ b3, float* __restrict__ out) {
    int i = blockIdx.x * blockDim.x + threadIdx.x;
    if (i >= NN * 32) return;
    int n = i >> 5, c = i & 31;
    const float* r = &g_out[n * 128];
    out[i] = 0.25f * (r[c] + r[32 + c] + r[64 + c] + r[96 + c]) + b3[c];
}

// -----------------------------------------------------------------------------
extern "C" void kernel_launch(void* const* d_in, const int* in_sizes, int n_in,
                              void* d_out, int out_size) {
    const float* x   = (const float*)d_in[0];
    const void*  ei  = d_in[1];
    const float* W1  = (const float*)d_in[2];
    const float* as1 = (const float*)d_in[3];
    const float* ad1 = (const float*)d_in[4];
    const float* b1  = (const float*)d_in[5];
    const float* W2  = (const float*)d_in[6];
    const float* as2 = (const float*)d_in[7];
    const float* ad2 = (const float*)d_in[8];
    const float* b2  = (const float*)d_in[9];
    const float* W3  = (const float*)d_in[10];
    const float* as3 = (const float*)d_in[11];
    const float* ad3 = (const float*)d_in[12];
    const float* b3  = (const float*)d_in[13];

    float *p_out, *p_ssum;
    cudaGetSymbolAddress((void**)&p_out, g_out);
    cudaGetSymbolAddress((void**)&p_ssum, g_ssum);

    detect_k<<<1, 256>>>((const unsigned int*)ei);

    // ---- layer 1: 128 -> 4x8 (concat 32), ELU ----
    gemm_att_k<128, 32, 8><<<NN / 4, 128>>>(x, W1, as1, ad1);
    zero_k<<<(NN * 4 + 255) / 256, 256>>>(p_ssum, NN * 4);
    zero_k<<<(NN * 32 + 255) / 256, 256>>>(p_out, NN * 32);
    edgeA_k<<<(EE + 255) / 256, 256>>>(ei);
    edgeB_k<32, 8><<<(EE * 8 + 255) / 256, 256>>>(ei);
    bias_elu_k<32><<<(NN * 32 + 255) / 256, 256>>>(b1);

    // ---- layer 2: 32 -> 4x32 (concat 128), ELU ----
    gemm_att_k<32, 128, 32><<<NN, 128>>>(p_out, W2, as2, ad2);
    zero_k<<<(NN * 4 + 255) / 256, 256>>>(p_ssum, NN * 4);
    zero_k<<<(NN * 128 + 255) / 256, 256>>>(p_out, NN * 128);
    edgeA_k<<<(EE + 255) / 256, 256>>>(ei);
    edgeB_k<128, 32><<<(EE * 32 + 255) / 256, 256>>>(ei);
    bias_elu_k<128><<<(NN * 128 + 255) / 256, 256>>>(b2);

    // ---- layer 3: 128 -> 4x32, mean over heads, + b3 ----
    gemm_att_k<128, 128, 32><<<NN, 128>>>(p_out, W3, as3, ad3);
    zero_k<<<(NN * 4 + 255) / 256, 256>>>(p_ssum, NN * 4);
    zero_k<<<(NN * 128 + 255) / 256, 256>>>(p_out, NN * 128);
    edgeA_k<<<(EE + 255) / 256, 256>>>(ei);
    edgeB_k<128, 32><<<(EE * 32 + 255) / 256, 256>>>(ei);
    final_k<<<(NN * 32 + 255) / 256, 256>>>(b3, (float*)d_out);
}

// round 12
// speedup vs baseline: 1.0012x; 1.0001x over previous
#include <cuda_runtime.h>

#define NN 50000
#define EE 800000

// ---------------- scratch (device globals; no allocations allowed) ----------
__device__ float g_h[NN * 128];      // transformed features of current layer [N, H*C]
__device__ float g_out[NN * 128];    // aggregated output / next-layer input
__device__ float g_asrc[NN * 4];     // per-head src attention logits
__device__ float g_adst[NN * 4];     // per-head dst attention logits
__device__ float g_ssum[NN * 4];     // per-head softmax denominators
__device__ int   g_is64;             // edge_index dtype flag (1 = int64, 0 = int32)

__device__ __forceinline__ float lrelu(float x) { return x > 0.f ? x : 0.2f * x; }

__device__ __forceinline__ int eidx(const void* ei, int pos, int is64) {
    if (is64) return (int)((const long long*)ei)[pos];
    return ((const int*)ei)[pos];
}

// vectorized fire-and-forget atomic add (sm_90+)
__device__ __forceinline__ void red4(float* addr, float a, float b, float c, float d) {
    asm volatile("red.global.add.v4.f32 [%0], {%1, %2, %3, %4};"
                 :: "l"(addr), "f"(a), "f"(b), "f"(c), "f"(d) : "memory");
}

// ---------------- dtype detection -------------------------------------------
// If edge_index is int64, all high 32-bit words are 0 (values < 50000, nonneg).
// If int32, the odd words are random node ids (~0 chance all 1024 are zero).
__global__ void detect_k(const unsigned int* ei) {
    __shared__ int any;
    if (threadIdx.x == 0) any = 0;
    __syncthreads();
    int bad = 0;
    for (int i = threadIdx.x; i < 1024; i += blockDim.x)
        if (ei[2 * i + 1] != 0u) bad = 1;
    if (bad) any = 1;
    __syncthreads();
    if (threadIdx.x == 0) g_is64 = any ? 0 : 1;
}

__global__ void zero_k(float* p, int n) {
    int i = blockIdx.x * blockDim.x + threadIdx.x;
    if (i < n) p[i] = 0.f;
}

// ---------------- fused GEMM + attention projections ------------------------
// h[n, :] = in[n, :] @ W ;  a_src[n,h] = <h[n,h,:], att_src[h,:]> (same for dst)
// block = 128 threads handles (128/HC) nodes; per-head reduce via shfl over C lanes.
template <int K, int HC, int C>
__global__ void gemm_att_k(const float* __restrict__ in, const float* __restrict__ W,
                           const float* __restrict__ ats, const float* __restrict__ atd) {
    constexpr int NPB = 128 / HC;
    __shared__ float s_in[NPB * K];
    int n0 = blockIdx.x * NPB;
    for (int i = threadIdx.x; i < NPB * K; i += 128)
        s_in[i] = in[(n0 + i / K) * K + (i % K)];
    __syncthreads();

    int local = threadIdx.x / HC;
    int col   = threadIdx.x % HC;
    int n     = n0 + local;

    float acc = 0.f;
#pragma unroll
    for (int k = 0; k < K; k++)
        acc += s_in[local * K + k] * W[k * HC + col];
    g_h[n * HC + col] = acc;

    float vs = acc * ats[col];
    float vd = acc * atd[col];
#pragma unroll
    for (int off = C / 2; off > 0; off >>= 1) {
        vs += __shfl_xor_sync(0xffffffffu, vs, off);
        vd += __shfl_xor_sync(0xffffffffu, vd, off);
    }
    if ((col & (C - 1)) == 0) {
        int head = col / C;
        g_asrc[n * 4 + head] = vs;
        g_adst[n * 4 + head] = vd;
    }
}

// ---------------- edge pass A: softmax denominators --------------------------
__global__ void edgeA_k(const void* __restrict__ ei) {
    int e = blockIdx.x * blockDim.x + threadIdx.x;
    if (e >= EE) return;
    int is64 = g_is64;
    int s = eidx(ei, e, is64);
    int d = eidx(ei, EE + e, is64);
    float4 as = *(const float4*)&g_asrc[s * 4];
    float4 ad = *(const float4*)&g_adst[d * 4];
    float px = __expf(lrelu(as.x + ad.x));
    float py = __expf(lrelu(as.y + ad.y));
    float pz = __expf(lrelu(as.z + ad.z));
    float pw = __expf(lrelu(as.w + ad.w));
    red4(&g_ssum[d * 4], px, py, pz, pw);
}

// ---------------- edge pass B: weighted message scatter -----------------------
// HC/4 threads per edge; each thread moves one float4 of h[src] into out[dst].
template <int HC, int C>
__global__ void edgeB_k(const void* __restrict__ ei) {
    constexpr int T = HC / 4;
    int t = blockIdx.x * blockDim.x + threadIdx.x;
    int e = t / T;
    if (e >= EE) return;
    int lane = t % T;
    int is64 = g_is64;
    int s = eidx(ei, e, is64);
    int d = eidx(ei, EE + e, is64);
    int head = (lane * 4) / C;
    float a  = g_asrc[s * 4 + head] + g_adst[d * 4 + head];
    float ss = g_ssum[d * 4 + head];
    float alpha = __expf(lrelu(a)) / (ss + 1e-16f);
    float4 hv = *(const float4*)&g_h[s * HC + lane * 4];
    red4(&g_out[d * HC + lane * 4],
         hv.x * alpha, hv.y * alpha, hv.z * alpha, hv.w * alpha);
}

// ---------------- bias + ELU (in place on g_out) -----------------------------
template <int HC>
__global__ void bias_elu_k(const float* __restrict__ bias) {
    int i = blockIdx.x * blockDim.x + threadIdx.x;
    if (i >= NN * HC) return;
    float v = g_out[i] + bias[i % HC];
    g_out[i] = v > 0.f ? v : expm1f(v);
}

// ---------------- final layer: head-mean + bias -> d_out ---------------------
__global__ void final_k(const float* __restrict__ b3, float* __restrict__ out) {
    int i = blockIdx.x * blockDim.x + threadIdx.x;
    if (i >= NN * 32) return;
    int n = i >> 5, c = i & 31;
    const float* r = &g_out[n * 128];
    out[i] = 0.25f * (r[c] + r[32 + c] + r[64 + c] + r[96 + c]) + b3[c];
}

// -----------------------------------------------------------------------------
extern "C" void kernel_launch(void* const* d_in, const int* in_sizes, int n_in,
                              void* d_out, int out_size) {
    const float* x   = (const float*)d_in[0];
    const void*  ei  = d_in[1];
    const float* W1  = (const float*)d_in[2];
    const float* as1 = (const float*)d_in[3];
    const float* ad1 = (const float*)d_in[4];
    const float* b1  = (const float*)d_in[5];
    const float* W2  = (const float*)d_in[6];
    const float* as2 = (const float*)d_in[7];
    const float* ad2 = (const float*)d_in[8];
    const float* b2  = (const float*)d_in[9];
    const float* W3  = (const float*)d_in[10];
    const float* as3 = (const float*)d_in[11];
    const float* ad3 = (const float*)d_in[12];
    const float* b3  = (const float*)d_in[13];

    float *p_out, *p_ssum;
    cudaGetSymbolAddress((void**)&p_out, g_out);
    cudaGetSymbolAddress((void**)&p_ssum, g_ssum);

    detect_k<<<1, 256>>>((const unsigned int*)ei);

    // ---- layer 1: 128 -> 4x8 (concat 32), ELU ----
    gemm_att_k<128, 32, 8><<<NN / 4, 128>>>(x, W1, as1, ad1);
    zero_k<<<(NN * 4 + 255) / 256, 256>>>(p_ssum, NN * 4);
    zero_k<<<(NN * 32 + 255) / 256, 256>>>(p_out, NN * 32);
    edgeA_k<<<(EE + 255) / 256, 256>>>(ei);
    edgeB_k<32, 8><<<(EE * 8 + 255) / 256, 256>>>(ei);
    bias_elu_k<32><<<(NN * 32 + 255) / 256, 256>>>(b1);

    // ---- layer 2: 32 -> 4x32 (concat 128), ELU ----
    gemm_att_k<32, 128, 32><<<NN, 128>>>(p_out, W2, as2, ad2);
    zero_k<<<(NN * 4 + 255) / 256, 256>>>(p_ssum, NN * 4);
    zero_k<<<(NN * 128 + 255) / 256, 256>>>(p_out, NN * 128);
    edgeA_k<<<(EE + 255) / 256, 256>>>(ei);
    edgeB_k<128, 32><<<(EE * 32 + 255) / 256, 256>>>(ei);
    bias_elu_k<128><<<(NN * 128 + 255) / 256, 256>>>(b2);

    // ---- layer 3: 128 -> 4x32, mean over heads, + b3 ----
    gemm_att_k<128, 128, 32><<<NN, 128>>>(p_out, W3, as3, ad3);
    zero_k<<<(NN * 4 + 255) / 256, 256>>>(p_ssum, NN * 4);
    zero_k<<<(NN * 128 + 255) / 256, 256>>>(p_out, NN * 128);
    edgeA_k<<<(EE + 255) / 256, 256>>>(ei);
    edgeB_k<128, 32><<<(EE * 32 + 255) / 256, 256>>>(ei);
    final_k<<<(NN * 32 + 255) / 256, 256>>>(b3, (float*)d_out);
}